// round 2
// baseline (speedup 1.0000x reference)
#include <cuda_runtime.h>
#include <math.h>

// Problem constants
#define L_SEQ 1024
#define B_SZ  16
#define D_SZ  1024
#define M_TOT (L_SEQ * B_SZ)     // 16384 rows of X
#define K_TOT D_SZ               // 1024
#define N_TOT (3 * D_SZ)         // 3072 cols of W
#define PLANE (M_TOT * D_SZ)     // 16,777,216 elements per plane

// Scratch: 3 planes (u0, sigmoid(u1+b1), sigmoid(u2+b2)), each [M_TOT, D] fp32.
// __device__ global => allowed (no runtime allocation).
__device__ float g_u[3ull * PLANE];

// ---------------------------------------------------------------------------
// GEMM: U = X @ W with fused bias + sigmoid epilogue, scattered into planes.
// Classic SIMT SGEMM: BM=128, BN=128, BK=16, 256 threads, 8x8 per thread.
// ---------------------------------------------------------------------------
#define BM 128
#define BN 128
#define BK 16
#define TM 8
#define TN 8

__device__ __forceinline__ float sigmoidf_(float v) {
    return 1.0f / (1.0f + expf(-v));
}

__global__ __launch_bounds__(256, 2)
void sru_gemm_kernel(const float* __restrict__ X,
                     const float* __restrict__ W,
                     const float* __restrict__ bias)
{
    __shared__ float As[BK][BM];   // A stored transposed
    __shared__ float Bs[BK][BN];

    const int bn = blockIdx.x;     // along N (24 blocks)
    const int bm = blockIdx.y;     // along M (128 blocks)
    const int tid = threadIdx.x;   // 0..255
    const int tx = tid % 16;       // N direction
    const int ty = tid / 16;       // M direction

    // A tile load mapping: 128 rows x 16 cols = 512 float4; 2 per thread
    const int arow = tid >> 2;        // 0..63 (+64 second iter)
    const int acol4 = (tid & 3) * 4;  // 0,4,8,12
    // B tile load mapping: 16 rows x 128 cols = 512 float4; 2 per thread
    const int brow = tid >> 5;        // 0..7 (+8 second iter)
    const int bcol4 = (tid & 31) * 4; // 0..124

    const float* Xb = X + (size_t)bm * BM * K_TOT;
    const float* Wb = W + (size_t)bn * BN;

    float acc[TM][TN];
    #pragma unroll
    for (int i = 0; i < TM; i++)
        #pragma unroll
        for (int j = 0; j < TN; j++) acc[i][j] = 0.0f;

    for (int k0 = 0; k0 < K_TOT; k0 += BK) {
        // Load A tile (transpose into As[k][m])
        #pragma unroll
        for (int r = 0; r < 2; r++) {
            int row = arow + r * 64;
            float4 a = *reinterpret_cast<const float4*>(Xb + (size_t)row * K_TOT + k0 + acol4);
            As[acol4 + 0][row] = a.x;
            As[acol4 + 1][row] = a.y;
            As[acol4 + 2][row] = a.z;
            As[acol4 + 3][row] = a.w;
        }
        // Load B tile
        #pragma unroll
        for (int r = 0; r < 2; r++) {
            int row = brow + r * 8;
            float4 b = *reinterpret_cast<const float4*>(Wb + (size_t)(k0 + row) * N_TOT + bcol4);
            *reinterpret_cast<float4*>(&Bs[row][bcol4]) = b;
        }
        __syncthreads();

        #pragma unroll
        for (int k = 0; k < BK; k++) {
            float a[TM], b[TN];
            #pragma unroll
            for (int i = 0; i < TM; i++) a[i] = As[k][ty * TM + i];
            #pragma unroll
            for (int j = 0; j < TN; j++) b[j] = Bs[k][tx * TN + j];
            #pragma unroll
            for (int i = 0; i < TM; i++)
                #pragma unroll
                for (int j = 0; j < TN; j++)
                    acc[i][j] = fmaf(a[i], b[j], acc[i][j]);
        }
        __syncthreads();
    }

    // Epilogue: n -> (d = n/3, gate j = n%3); fuse bias + sigmoid for gates.
    const int m0 = bm * BM + ty * TM;
    const int n0 = bn * BN + tx * TN;
    #pragma unroll
    for (int i = 0; i < TM; i++) {
        const int m = m0 + i;
        #pragma unroll
        for (int j = 0; j < TN; j++) {
            const int n = n0 + j;
            const int gate = n % 3;
            const int d = n / 3;
            float v = acc[i][j];
            size_t off = (size_t)m * D_SZ + d;
            if (gate == 0) {
                g_u[off] = v;
            } else if (gate == 1) {
                g_u[PLANE + off] = sigmoidf_(v + bias[d]);
            } else {
                g_u[2ull * PLANE + off] = sigmoidf_(v + bias[D_SZ + d]);
            }
        }
    }
}

// ---------------------------------------------------------------------------
// Scan: one thread per (b,d) lane; 1024 sequential steps.
// Plane offset for step t is t*(B*D) + idx  (coalesced across the warp).
// ---------------------------------------------------------------------------
__global__ __launch_bounds__(128)
void sru_scan_kernel(const float* __restrict__ x,
                     const float* __restrict__ c0,
                     float* __restrict__ out)
{
    const int idx = blockIdx.x * blockDim.x + threadIdx.x;   // 0..B*D-1
    if (idx >= B_SZ * D_SZ) return;

    float c = c0[idx];

    const float* __restrict__ u0 = g_u;
    const float* __restrict__ g1 = g_u + PLANE;
    const float* __restrict__ g2 = g_u + 2ull * PLANE;

    #pragma unroll 8
    for (int t = 0; t < L_SEQ; t++) {
        const size_t o = (size_t)t * (B_SZ * D_SZ) + idx;
        const float u0v = u0[o];
        const float g1v = g1[o];
        const float g2v = g2[o];
        const float xv  = x[o];
        c = (c - u0v) * g1v + u0v;
        const float h = (tanhf(c) - xv) * g2v + xv;
        out[o] = h;
    }
    out[(size_t)PLANE + idx] = c;   // c_last
}

// ---------------------------------------------------------------------------
// Launch
// ---------------------------------------------------------------------------
extern "C" void kernel_launch(void* const* d_in, const int* in_sizes, int n_in,
                              void* d_out, int out_size)
{
    const float* x      = (const float*)d_in[0];  // (L,B,D)
    const float* weight = (const float*)d_in[1];  // (D, 3D)
    const float* bias   = (const float*)d_in[2];  // (2D)
    const float* c0     = (const float*)d_in[3];  // (B,D)
    float* out = (float*)d_out;                   // h (L*B*D) then c_last (B*D)

    dim3 gemm_grid(N_TOT / BN, M_TOT / BM);       // (24, 128)
    sru_gemm_kernel<<<gemm_grid, 256>>>(x, weight, bias);

    sru_scan_kernel<<<128, 128>>>(x, c0, out);
}